// round 4
// baseline (speedup 1.0000x reference)
#include <cuda_runtime.h>
#include <cuda_pipeline.h>
#include <mma.h>
#include <cstdint>
#include <cstddef>

using namespace nvcuda;

#define L_  6
#define B_  8
#define Q_  2048
#define C_  256
#define P_  128
#define FF_ 1024
#define R_  (B_*Q_)   // 16384 rows

static const size_t INTERM_OFF = 0;
static const size_t REFS_OFF   = (size_t)L_*R_*C_;                 // 25,165,824
static const size_t LOGITS_OFF = REFS_OFF + (size_t)(L_+1)*R_*3;   // 25,509,888

// ---------------- device state (no allocations allowed) ----------------
__device__ float g_query [R_*C_];
__device__ float g_qpos  [R_*C_];
__device__ float g_qsum  [R_*C_];
__device__ float g_H     [R_*FF_];
__device__ float g_logits[R_*P_];
__device__ float g_S     [R_*P_];
__device__ float g_probs [R_*P_];
__device__ float g_lnpos [R_*C_];
__device__ float g_t1    [R_*C_];
__device__ float g_t2    [R_*C_];
__device__ float g_ref   [R_*3];

// ---------------- reductions ----------------
__device__ __forceinline__ float warp_sum(float v){
#pragma unroll
    for (int o = 16; o; o >>= 1) v += __shfl_xor_sync(0xffffffffu, v, o);
    return v;
}
__device__ __forceinline__ float warp_max(float v){
#pragma unroll
    for (int o = 16; o; o >>= 1) v = fmaxf(v, __shfl_xor_sync(0xffffffffu, v, o));
    return v;
}

// ---------------- pipelined TF32 tensor-core GEMM ----------------
// C = epi(A @ B + bias [+ Cres]); fp32 in global, raw bits into HMMA.TF32
// (hardware truncation). BM=BN=128, BK=32, 2-stage cp.async pipeline.
// 256 threads = 8 warps (2x4); warp tile 64x32 = 4x2 wmma m16n16k8 frags.
// EPI: 0=relu(.+b), 1=Cres+.+b, 2=.+b
#define GA_LD 36     // As row stride (32 + 4 pad), 144B, 16B-aligned
#define GB_LD 132    // Bs row stride (128 + 4 pad), 528B, 16B-aligned
#define GEMM_SMEM_FLOATS (2*128*GA_LD + 2*32*GB_LD + 16*128)
#define GEMM_SMEM_BYTES  (GEMM_SMEM_FLOATS*4)

template<int EPI>
__global__ __launch_bounds__(256, 2)
void tgemm(int M, int N, int K,
           const float* __restrict__ A,
           const float* __restrict__ Bm, const float* __restrict__ bias,
           const float* __restrict__ Cres, float* __restrict__ Cout)
{
    const int BM = 128, BN = 128, BK = 32;
    extern __shared__ float sm[];
    float* Asm    = sm;                              // [2][128][GA_LD]
    float* Bsm    = sm + 2*128*GA_LD;                // [2][32][GB_LD]
    float* bias_s = sm + 2*128*GA_LD + 2*32*GB_LD;   // [16][128]

    const int tid = threadIdx.x;
    const int wid = tid >> 5;
    const int bm = blockIdx.y, bn = blockIdx.x;
    const int warp_m = wid >> 2;          // 0..1 -> 64 rows
    const int warp_n = wid & 3;           // 0..3 -> 32 cols

    // bias replicated tile
    for (int idx = tid; idx < 16 * BN; idx += 256)
        bias_s[idx] = bias[bn * BN + (idx & 127)];

    // ---- stage loader (cp.async) ----
    auto load_stage = [&](int s, int k0) {
#pragma unroll
        for (int it = 0; it < 4; it++) {
            int idx = tid + it * 256;
            // A: 128 rows x 32 cols -> 1024 float4
            int ar = idx >> 3, ac = (idx & 7) * 4;
            __pipeline_memcpy_async(
                Asm + ((size_t)s*128 + ar)*GA_LD + ac,
                A + (size_t)(bm*BM + ar)*K + k0 + ac, 16);
            // B: 32 rows x 128 cols -> 1024 float4
            int br = idx >> 5, bc = (idx & 31) * 4;
            __pipeline_memcpy_async(
                Bsm + ((size_t)s*32 + br)*GB_LD + bc,
                Bm + (size_t)(k0 + br)*N + bn*BN + bc, 16);
        }
    };

    // prefetch stage 0
    load_stage(0, 0);
    __pipeline_commit();
    __syncthreads();   // bias_s visible

    // init accumulators from bias
    wmma::fragment<wmma::accumulator, 16, 16, 8, float> acc[4][2];
    {
        wmma::fragment<wmma::accumulator, 16, 16, 8, float> bf[2];
#pragma unroll
        for (int j = 0; j < 2; j++)
            wmma::load_matrix_sync(bf[j], &bias_s[warp_n*32 + j*16], BN,
                                   wmma::mem_row_major);
#pragma unroll
        for (int i = 0; i < 4; i++)
#pragma unroll
            for (int j = 0; j < 2; j++)
#pragma unroll
                for (int e = 0; e < bf[j].num_elements; e++)
                    acc[i][j].x[e] = bf[j].x[e];
    }

    int s = 0;
    for (int k0 = 0; k0 < K; k0 += BK, s ^= 1) {
        if (k0 + BK < K) load_stage(s ^ 1, k0 + BK);
        __pipeline_commit();
        __pipeline_wait_prior(1);
        __syncthreads();
        // compute stage s
#pragma unroll
        for (int kk = 0; kk < BK; kk += 8) {
            wmma::fragment<wmma::matrix_a, 16, 16, 8, wmma::precision::tf32, wmma::row_major> af[4];
            wmma::fragment<wmma::matrix_b, 16, 16, 8, wmma::precision::tf32, wmma::row_major> bfr[2];
#pragma unroll
            for (int i = 0; i < 4; i++)
                wmma::load_matrix_sync(af[i],
                    Asm + ((size_t)s*128 + warp_m*64 + i*16)*GA_LD + kk, GA_LD);
#pragma unroll
            for (int j = 0; j < 2; j++)
                wmma::load_matrix_sync(bfr[j],
                    Bsm + ((size_t)s*32 + kk)*GB_LD + warp_n*32 + j*16, GB_LD);
#pragma unroll
            for (int i = 0; i < 4; i++)
#pragma unroll
                for (int j = 0; j < 2; j++)
                    wmma::mma_sync(acc[i][j], af[i], bfr[j], acc[i][j]);
        }
        __syncthreads();
    }

    // epilogue
#pragma unroll
    for (int i = 0; i < 4; i++) {
        int row = bm * BM + warp_m * 64 + i * 16;
#pragma unroll
        for (int j = 0; j < 2; j++) {
            int col = bn * BN + warp_n * 32 + j * 16;
            if (EPI == 0) {
#pragma unroll
                for (int e = 0; e < acc[i][j].num_elements; e++)
                    acc[i][j].x[e] = fmaxf(acc[i][j].x[e], 0.f);
            } else if (EPI == 1) {
                wmma::fragment<wmma::accumulator, 16, 16, 8, float> cf;
                wmma::load_matrix_sync(cf, Cres + (size_t)row * N + col, N,
                                       wmma::mem_row_major);
#pragma unroll
                for (int e = 0; e < cf.num_elements; e++)
                    acc[i][j].x[e] += cf.x[e];
            }
            wmma::store_matrix_sync(Cout + (size_t)row * N + col, acc[i][j], N,
                                    wmma::mem_row_major);
        }
    }
}

// ---------------- logits init + qsum init ----------------
__global__ void init_kernel(const float* __restrict__ p, float* __restrict__ lg,
                            const float* __restrict__ q, const float* __restrict__ qp,
                            float* __restrict__ qsum)
{
    int i = blockIdx.x * blockDim.x + threadIdx.x;
    if (i < R_*P_) lg[i] = logf(fmaxf(p[i], 1e-8f));
    if (i < R_*C_) qsum[i] = q[i] + qp[i];
}

// ---------------- plain row LN (256 cols, 128 threads) ----------------
__global__ void ln_rows(const float* __restrict__ in, float* __restrict__ out)
{
    int row = blockIdx.x, t = threadIdx.x;
    int w = t >> 5, lane = t & 31;
    __shared__ float sr[8];
    float x0 = in[(size_t)row*C_ + t];
    float x1 = in[(size_t)row*C_ + 128 + t];
    float s1 = warp_sum(x0 + x1);
    float s2 = warp_sum(x0*x0 + x1*x1);
    if (lane == 0) { sr[w] = s1; sr[4+w] = s2; }
    __syncthreads();
    float m  = (sr[0]+sr[1]+sr[2]+sr[3]) * (1.f/256.f);
    float vv = (sr[4]+sr[5]+sr[6]+sr[7]) * (1.f/256.f) - m*m;
    float r  = rsqrtf(vv + 1e-5f);
    out[(size_t)row*C_ + t]       = (x0 - m) * r;
    out[(size_t)row*C_ + 128 + t] = (x1 - m) * r;
}

// ---------------- per-row fused: LN->interm, logits+softmax, ref einsum ----------------
__global__ void row_kernel(int layer,
                           const float* __restrict__ query,
                           const float* __restrict__ S,
                           const float* __restrict__ coords,
                           const int* __restrict__ mask,
                           const float* __restrict__ pn_scale,
                           const float* __restrict__ pn_bias,
                           float* __restrict__ logits_st,
                           float* __restrict__ probs,
                           float* __restrict__ ref_st,
                           float* __restrict__ out)
{
    int row = blockIdx.x, t = threadIdx.x;
    int w = t >> 5, lane = t & 31;
    __shared__ float sr[12];

    // --- layernorm of query -> interm output ---
    float x0 = query[(size_t)row*C_ + t];
    float x1 = query[(size_t)row*C_ + 128 + t];
    float s1 = warp_sum(x0 + x1);
    float s2 = warp_sum(x0*x0 + x1*x1);
    if (lane == 0) { sr[w] = s1; sr[4+w] = s2; }
    __syncthreads();
    float m    = (sr[0]+sr[1]+sr[2]+sr[3]) * (1.f/256.f);
    float var  = (sr[4]+sr[5]+sr[6]+sr[7]) * (1.f/256.f) - m*m;
    float rstd = rsqrtf(var + 1e-5f);
    size_t ib = INTERM_OFF + (size_t)layer*R_*C_ + (size_t)row*C_;
    out[ib + t]       = (x0 - m)*rstd*pn_scale[t]       + pn_bias[t];
    out[ib + 128 + t] = (x1 - m)*rstd*pn_scale[128 + t] + pn_bias[128 + t];

    // --- masked logits residual update ---
    float mf = mask[row] ? 1.f : 0.f;
    size_t li = (size_t)row*P_ + t;
    float lg = logits_st[li] + S[li] * mf;
    logits_st[li] = lg;
    out[LOGITS_OFF + (size_t)layer*R_*P_ + li] = lg;

    // --- softmax over 128 ---
    float mx = warp_max(lg);
    __syncthreads();
    if (lane == 0) sr[w] = mx;
    __syncthreads();
    mx = fmaxf(fmaxf(sr[0], sr[1]), fmaxf(sr[2], sr[3]));
    float e = __expf(lg - mx);
    float se = warp_sum(e);
    __syncthreads();
    if (lane == 0) sr[w] = se;
    __syncthreads();
    se = sr[0]+sr[1]+sr[2]+sr[3];
    float p = e / se;
    probs[li] = p;

    // --- dyn_ref = probs @ coords[row] (128x3) ---
    const float* cr = coords + (size_t)row*P_*3 + (size_t)t*3;
    float r0 = warp_sum(p * cr[0]);
    float r1 = warp_sum(p * cr[1]);
    float r2 = warp_sum(p * cr[2]);
    __syncthreads();
    if (lane == 0) { sr[w] = r0; sr[4+w] = r1; sr[8+w] = r2; }
    __syncthreads();
    if (t == 0) {
        float d0 = sr[0]+sr[1]+sr[2]+sr[3];
        float d1 = sr[4]+sr[5]+sr[6]+sr[7];
        float d2 = sr[8]+sr[9]+sr[10]+sr[11];
        float o0, o1, o2;
        if (mf > 0.f) { o0 = d0; o1 = d1; o2 = d2; }
        else { o0 = ref_st[row*3]; o1 = ref_st[row*3+1]; o2 = ref_st[row*3+2]; }
        ref_st[row*3] = o0; ref_st[row*3+1] = o1; ref_st[row*3+2] = o2;
        size_t rb = REFS_OFF + (size_t)(layer+1)*R_*3 + (size_t)row*3;
        out[rb] = o0; out[rb+1] = o1; out[rb+2] = o2;
    }
}

// ---------------- layer tail: masked qpos update + qsum = q + qpos ----------------
__global__ void layer_tail(const float* __restrict__ q,
                           const float* __restrict__ t1, const float* __restrict__ t2,
                           const float* __restrict__ lnp, const int* __restrict__ mask,
                           float* __restrict__ qpos, float* __restrict__ qsum)
{
    int idx = blockIdx.x * blockDim.x + threadIdx.x;
    if (idx >= R_*C_) return;
    int row = idx >> 8;
    float qp = qpos[idx];
    if (mask[row]) { qp = lnp[idx] * t1[idx] + t2[idx]; qpos[idx] = qp; }
    qsum[idx] = q[idx] + qp;
}

// ---------------- host ----------------
extern "C" void kernel_launch(void* const* d_in, const int* in_sizes, int n_in,
                              void* d_out, int out_size)
{
    const float*   query      = (const float*)d_in[0];
    const float*   query_pos  = (const float*)d_in[1];
    const float*   refpts     = (const float*)d_in[2];
    const float*   coords     = (const float*)d_in[3];
    const float*   dprobs     = (const float*)d_in[4];
    const int*     mask       = (const int*)d_in[5];
    const float*   layer_w1   = (const float*)d_in[6];
    const float*   layer_b1   = (const float*)d_in[7];
    const float*   layer_w2   = (const float*)d_in[8];
    const float*   layer_b2   = (const float*)d_in[9];
    const float*   prob_w     = (const float*)d_in[10];
    const float*   prob_b     = (const float*)d_in[11];
    const float*   pos_w      = (const float*)d_in[12];
    const float*   pos_b      = (const float*)d_in[13];
    const float*   g_w        = (const float*)d_in[14];
    const float*   g_b        = (const float*)d_in[15];
    const float*   be_w       = (const float*)d_in[16];
    const float*   be_b       = (const float*)d_in[17];
    const float*   pn_scale   = (const float*)d_in[18];
    const float*   pn_bias    = (const float*)d_in[19];
    float* out = (float*)d_out;

    float *q, *qp, *qs, *H, *lg, *S, *pb, *lnp, *t1, *t2, *ref;
    cudaGetSymbolAddress((void**)&q,   g_query);
    cudaGetSymbolAddress((void**)&qp,  g_qpos);
    cudaGetSymbolAddress((void**)&qs,  g_qsum);
    cudaGetSymbolAddress((void**)&H,   g_H);
    cudaGetSymbolAddress((void**)&lg,  g_logits);
    cudaGetSymbolAddress((void**)&S,   g_S);
    cudaGetSymbolAddress((void**)&pb,  g_probs);
    cudaGetSymbolAddress((void**)&lnp, g_lnpos);
    cudaGetSymbolAddress((void**)&t1,  g_t1);
    cudaGetSymbolAddress((void**)&t2,  g_t2);
    cudaGetSymbolAddress((void**)&ref, g_ref);

    cudaFuncSetAttribute(tgemm<0>, cudaFuncAttributeMaxDynamicSharedMemorySize, GEMM_SMEM_BYTES);
    cudaFuncSetAttribute(tgemm<1>, cudaFuncAttributeMaxDynamicSharedMemorySize, GEMM_SMEM_BYTES);
    cudaFuncSetAttribute(tgemm<2>, cudaFuncAttributeMaxDynamicSharedMemorySize, GEMM_SMEM_BYTES);

    // init state
    cudaMemcpyAsync(q,   query,     (size_t)R_*C_*4, cudaMemcpyDeviceToDevice);
    cudaMemcpyAsync(qp,  query_pos, (size_t)R_*C_*4, cudaMemcpyDeviceToDevice);
    cudaMemcpyAsync(ref, refpts,    (size_t)R_*3*4,  cudaMemcpyDeviceToDevice);
    cudaMemcpyAsync(out + REFS_OFF, refpts, (size_t)R_*3*4, cudaMemcpyDeviceToDevice);

    init_kernel<<<(R_*C_ + 255)/256, 256>>>(dprobs, lg, query, query_pos, qs);

    // pos_base = coords.reshape(R,384) @ pos_w + pos_b ; then LN -> g_lnpos
    tgemm<2><<<dim3(C_/128, R_/128), 256, GEMM_SMEM_BYTES>>>(R_, C_, P_*3, coords,
                                                             pos_w, pos_b, nullptr, t1);
    ln_rows<<<R_, 128>>>(t1, lnp);

    for (int i = 0; i < L_; i++) {
        // H = relu(qsum @ W1 + b1)
        tgemm<0><<<dim3(FF_/128, R_/128), 256, GEMM_SMEM_BYTES>>>(R_, FF_, C_,
            qs, layer_w1 + (size_t)i*C_*FF_, layer_b1 + (size_t)i*FF_, nullptr, H);
        // q = q + H @ W2 + b2
        tgemm<1><<<dim3(C_/128, R_/128), 256, GEMM_SMEM_BYTES>>>(R_, C_, FF_,
            H, layer_w2 + (size_t)i*FF_*C_, layer_b2 + (size_t)i*C_, q, q);
        // S = q @ prob_w + prob_b
        tgemm<2><<<dim3(P_/128, R_/128), 256, GEMM_SMEM_BYTES>>>(R_, P_, C_,
            q, prob_w + (size_t)i*C_*P_, prob_b + (size_t)i*P_, nullptr, S);
        // per-row fused ops
        row_kernel<<<R_, 128>>>(i, q, S, coords, mask, pn_scale, pn_bias,
                                lg, pb, ref, out);
        // t1 = probs @ g_w + g_b ; t2 = probs @ be_w + be_b
        tgemm<2><<<dim3(C_/128, R_/128), 256, GEMM_SMEM_BYTES>>>(R_, C_, P_,
            pb, g_w, g_b, nullptr, t1);
        tgemm<2><<<dim3(C_/128, R_/128), 256, GEMM_SMEM_BYTES>>>(R_, C_, P_,
            pb, be_w, be_b, nullptr, t2);
        // qpos masked update + qsum for next layer
        layer_tail<<<(R_*C_ + 255)/256, 256>>>(q, t1, t2, lnp, mask, qp, qs);
    }
    (void)in_sizes; (void)n_in; (void)out_size;
}

// round 5
// speedup vs baseline: 1.0200x; 1.0200x over previous
#include <cuda_runtime.h>
#include <cuda_pipeline.h>
#include <mma.h>
#include <cstdint>
#include <cstddef>

using namespace nvcuda;

#define L_  6
#define B_  8
#define Q_  2048
#define C_  256
#define P_  128
#define FF_ 1024
#define R_  (B_*Q_)   // 16384 rows

static const size_t INTERM_OFF = 0;
static const size_t REFS_OFF   = (size_t)L_*R_*C_;                 // 25,165,824
static const size_t LOGITS_OFF = REFS_OFF + (size_t)(L_+1)*R_*3;   // 25,509,888

// ---------------- device state (no allocations allowed) ----------------
__device__ float g_query [R_*C_];
__device__ float g_qpos  [R_*C_];
__device__ float g_qsum  [R_*C_];
__device__ float g_H     [R_*FF_];
__device__ float g_logits[R_*P_];
__device__ float g_S     [R_*P_];
__device__ float g_probs [R_*P_];
__device__ float g_lnpos [R_*C_];
__device__ float g_t12   [R_*512];   // [t1 | t2] fused, also pos_base scratch
__device__ float g_ref   [R_*3];
__device__ float g_w12   [P_*512];   // [g_w | be_w] packed
__device__ float g_b12   [512];      // [g_b | be_b] packed

// ---------------- reductions ----------------
__device__ __forceinline__ float warp_sum(float v){
#pragma unroll
    for (int o = 16; o; o >>= 1) v += __shfl_xor_sync(0xffffffffu, v, o);
    return v;
}
__device__ __forceinline__ float warp_max(float v){
#pragma unroll
    for (int o = 16; o; o >>= 1) v = fmaxf(v, __shfl_xor_sync(0xffffffffu, v, o));
    return v;
}

// ---------------- pipelined TF32 GEMM, 64x64 warp tiles ----------------
// C = epi(A @ B + bias [+ Cres]); fp32 in global, raw bits into HMMA.TF32.
// BM=BN=128, BK=32, 3-stage cp.async. 128 threads = 4 warps (2x2), each 64x64
// = 4x4 wmma m16n16k8 fragments. Epilogue via smem for coalesced stores.
// EPI: 0=relu(.+b), 1=Cres+.+b, 2=.+b
#define GA_LD 36     // As row stride (32 + 4)
#define GB_LD 132    // Bs row stride (128 + 4)
#define ST_A (128*GA_LD)
#define ST_B (32*GB_LD)
#define GEMM_SMEM_FLOATS (3*ST_A + 3*ST_B)
#define GEMM_SMEM_BYTES  (GEMM_SMEM_FLOATS*4)
#define CT_LD 132

template<int EPI>
__global__ __launch_bounds__(128)
void tgemm(int M, int N, int K,
           const float* __restrict__ A,
           const float* __restrict__ Bm, const float* __restrict__ bias,
           const float* __restrict__ Cres, float* __restrict__ Cout)
{
    const int BM = 128, BN = 128, BK = 32;
    extern __shared__ float sm[];
    float* Asm = sm;              // [3][128][GA_LD]
    float* Bsm = sm + 3*ST_A;     // [3][32][GB_LD]

    const int tid = threadIdx.x;
    const int wid = tid >> 5;
    const int bm = blockIdx.y, bn = blockIdx.x;
    const int warp_m = wid >> 1;          // 0..1 -> 64 rows
    const int warp_n = wid & 1;           // 0..1 -> 64 cols

    // ---- stage loader (cp.async), 128 threads ----
    auto load_stage = [&](int s, int k0) {
#pragma unroll
        for (int it = 0; it < 8; it++) {
            int idx = tid + it * 128;
            // A: 128 x 32 -> 1024 float4
            int ar = idx >> 3, ac = (idx & 7) * 4;
            __pipeline_memcpy_async(
                Asm + (size_t)s*ST_A + ar*GA_LD + ac,
                A + (size_t)(bm*BM + ar)*K + k0 + ac, 16);
            // B: 32 x 128 -> 1024 float4
            int br = idx >> 5, bc = (idx & 31) * 4;
            __pipeline_memcpy_async(
                Bsm + (size_t)s*ST_B + br*GB_LD + bc,
                Bm + (size_t)(k0 + br)*N + bn*BN + bc, 16);
        }
    };

    const int nIter = K / BK;
    load_stage(0, 0);
    __pipeline_commit();
    if (nIter > 1) load_stage(1, BK);
    __pipeline_commit();

    wmma::fragment<wmma::accumulator, 16, 16, 8, float> acc[4][4];
#pragma unroll
    for (int i = 0; i < 4; i++)
#pragma unroll
        for (int j = 0; j < 4; j++)
            wmma::fill_fragment(acc[i][j], 0.f);

    for (int it = 0; it < nIter; it++) {
        if (it + 2 < nIter) load_stage((it + 2) % 3, (it + 2) * BK);
        __pipeline_commit();
        __pipeline_wait_prior(2);
        __syncthreads();
        const float* As = Asm + (size_t)(it % 3) * ST_A;
        const float* Bs = Bsm + (size_t)(it % 3) * ST_B;
#pragma unroll
        for (int kk = 0; kk < BK; kk += 8) {
            wmma::fragment<wmma::matrix_a, 16, 16, 8, wmma::precision::tf32, wmma::row_major> af[4];
            wmma::fragment<wmma::matrix_b, 16, 16, 8, wmma::precision::tf32, wmma::row_major> bf[4];
#pragma unroll
            for (int i = 0; i < 4; i++)
                wmma::load_matrix_sync(af[i], As + (warp_m*64 + i*16)*GA_LD + kk, GA_LD);
#pragma unroll
            for (int j = 0; j < 4; j++)
                wmma::load_matrix_sync(bf[j], Bs + (size_t)kk*GB_LD + warp_n*64 + j*16, GB_LD);
#pragma unroll
            for (int i = 0; i < 4; i++)
#pragma unroll
                for (int j = 0; j < 4; j++)
                    wmma::mma_sync(acc[i][j], af[i], bf[j], acc[i][j]);
        }
        __syncthreads();
    }

    // ---- epilogue via smem (Ct overlaps pipeline buffers; all loads done) ----
    float* Ct = sm;   // [128][CT_LD]
#pragma unroll
    for (int i = 0; i < 4; i++)
#pragma unroll
        for (int j = 0; j < 4; j++)
            wmma::store_matrix_sync(
                Ct + (size_t)(warp_m*64 + i*16)*CT_LD + warp_n*64 + j*16,
                acc[i][j], CT_LD, wmma::mem_row_major);
    __syncthreads();

    {
        int r = tid;                       // one row per thread
        int grow = bm * BM + r;
        float* dst = Cout + (size_t)grow * N + bn * BN;
        const float* resp = (EPI == 1) ? (Cres + (size_t)grow * N + bn * BN) : nullptr;
        const float* bp = bias + bn * BN;
#pragma unroll 8
        for (int c = 0; c < BN; c += 4) {
            float4 v = *(const float4*)&Ct[(size_t)r * CT_LD + c];
            float4 b = *(const float4*)&bp[c];
            v.x += b.x; v.y += b.y; v.z += b.z; v.w += b.w;
            if (EPI == 0) {
                v.x = fmaxf(v.x, 0.f); v.y = fmaxf(v.y, 0.f);
                v.z = fmaxf(v.z, 0.f); v.w = fmaxf(v.w, 0.f);
            } else if (EPI == 1) {
                float4 cr = *(const float4*)&resp[c];
                v.x += cr.x; v.y += cr.y; v.z += cr.z; v.w += cr.w;
            }
            *(float4*)&dst[c] = v;
        }
    }
}

// ---------------- pack [g_w|be_w], [g_b|be_b] ----------------
__global__ void pack_gb(const float* __restrict__ gw, const float* __restrict__ bew,
                        const float* __restrict__ gb, const float* __restrict__ beb,
                        float* __restrict__ w12, float* __restrict__ b12)
{
    int idx = blockIdx.x * blockDim.x + threadIdx.x;
    if (idx < P_ * 512) {
        int row = idx >> 9, col = idx & 511;
        w12[idx] = (col < 256) ? gw[row * 256 + col] : bew[row * 256 + col - 256];
    }
    if (idx < 512) b12[idx] = (idx < 256) ? gb[idx] : beb[idx - 256];
}

// ---------------- logits init + qsum init ----------------
__global__ void init_kernel(const float* __restrict__ p, float* __restrict__ lg,
                            const float* __restrict__ q, const float* __restrict__ qp,
                            float* __restrict__ qsum)
{
    int i = blockIdx.x * blockDim.x + threadIdx.x;
    if (i < R_*P_) lg[i] = logf(fmaxf(p[i], 1e-8f));
    if (i < R_*C_) qsum[i] = q[i] + qp[i];
}

// ---------------- plain row LN (256 cols, 128 threads) ----------------
__global__ void ln_rows(const float* __restrict__ in, float* __restrict__ out)
{
    int row = blockIdx.x, t = threadIdx.x;
    int w = t >> 5, lane = t & 31;
    __shared__ float sr[8];
    float x0 = in[(size_t)row*C_ + t];
    float x1 = in[(size_t)row*C_ + 128 + t];
    float s1 = warp_sum(x0 + x1);
    float s2 = warp_sum(x0*x0 + x1*x1);
    if (lane == 0) { sr[w] = s1; sr[4+w] = s2; }
    __syncthreads();
    float m  = (sr[0]+sr[1]+sr[2]+sr[3]) * (1.f/256.f);
    float vv = (sr[4]+sr[5]+sr[6]+sr[7]) * (1.f/256.f) - m*m;
    float r  = rsqrtf(vv + 1e-5f);
    out[(size_t)row*C_ + t]       = (x0 - m) * r;
    out[(size_t)row*C_ + 128 + t] = (x1 - m) * r;
}

// ---------------- per-row fused: LN->interm, logits+softmax, ref einsum ----------------
__global__ void row_kernel(int layer,
                           const float* __restrict__ query,
                           const float* __restrict__ S,
                           const float* __restrict__ coords,
                           const int* __restrict__ mask,
                           const float* __restrict__ pn_scale,
                           const float* __restrict__ pn_bias,
                           float* __restrict__ logits_st,
                           float* __restrict__ probs,
                           float* __restrict__ ref_st,
                           float* __restrict__ out)
{
    int row = blockIdx.x, t = threadIdx.x;
    int w = t >> 5, lane = t & 31;
    __shared__ float sr[12];

    float x0 = query[(size_t)row*C_ + t];
    float x1 = query[(size_t)row*C_ + 128 + t];
    float s1 = warp_sum(x0 + x1);
    float s2 = warp_sum(x0*x0 + x1*x1);
    if (lane == 0) { sr[w] = s1; sr[4+w] = s2; }
    __syncthreads();
    float m    = (sr[0]+sr[1]+sr[2]+sr[3]) * (1.f/256.f);
    float var  = (sr[4]+sr[5]+sr[6]+sr[7]) * (1.f/256.f) - m*m;
    float rstd = rsqrtf(var + 1e-5f);
    size_t ib = INTERM_OFF + (size_t)layer*R_*C_ + (size_t)row*C_;
    out[ib + t]       = (x0 - m)*rstd*pn_scale[t]       + pn_bias[t];
    out[ib + 128 + t] = (x1 - m)*rstd*pn_scale[128 + t] + pn_bias[128 + t];

    float mf = mask[row] ? 1.f : 0.f;
    size_t li = (size_t)row*P_ + t;
    float lg = logits_st[li] + S[li] * mf;
    logits_st[li] = lg;
    out[LOGITS_OFF + (size_t)layer*R_*P_ + li] = lg;

    float mx = warp_max(lg);
    __syncthreads();
    if (lane == 0) sr[w] = mx;
    __syncthreads();
    mx = fmaxf(fmaxf(sr[0], sr[1]), fmaxf(sr[2], sr[3]));
    float e = __expf(lg - mx);
    float se = warp_sum(e);
    __syncthreads();
    if (lane == 0) sr[w] = se;
    __syncthreads();
    se = sr[0]+sr[1]+sr[2]+sr[3];
    float p = e / se;
    probs[li] = p;

    const float* cr = coords + (size_t)row*P_*3 + (size_t)t*3;
    float r0 = warp_sum(p * cr[0]);
    float r1 = warp_sum(p * cr[1]);
    float r2 = warp_sum(p * cr[2]);
    __syncthreads();
    if (lane == 0) { sr[w] = r0; sr[4+w] = r1; sr[8+w] = r2; }
    __syncthreads();
    if (t == 0) {
        float d0 = sr[0]+sr[1]+sr[2]+sr[3];
        float d1 = sr[4]+sr[5]+sr[6]+sr[7];
        float d2 = sr[8]+sr[9]+sr[10]+sr[11];
        float o0, o1, o2;
        if (mf > 0.f) { o0 = d0; o1 = d1; o2 = d2; }
        else { o0 = ref_st[row*3]; o1 = ref_st[row*3+1]; o2 = ref_st[row*3+2]; }
        ref_st[row*3] = o0; ref_st[row*3+1] = o1; ref_st[row*3+2] = o2;
        size_t rb = REFS_OFF + (size_t)(layer+1)*R_*3 + (size_t)row*3;
        out[rb] = o0; out[rb+1] = o1; out[rb+2] = o2;
    }
}

// ---------------- layer tail: masked qpos update + qsum = q + qpos ----------------
__global__ void layer_tail(const float* __restrict__ q,
                           const float* __restrict__ t12,
                           const float* __restrict__ lnp, const int* __restrict__ mask,
                           float* __restrict__ qpos, float* __restrict__ qsum)
{
    int idx = blockIdx.x * blockDim.x + threadIdx.x;
    if (idx >= R_*C_) return;
    int row = idx >> 8, c = idx & 255;
    float qp = qpos[idx];
    if (mask[row]) {
        float t1 = t12[(size_t)row*512 + c];
        float t2 = t12[(size_t)row*512 + 256 + c];
        qp = lnp[idx] * t1 + t2;
        qpos[idx] = qp;
    }
    qsum[idx] = q[idx] + qp;
}

// ---------------- host ----------------
extern "C" void kernel_launch(void* const* d_in, const int* in_sizes, int n_in,
                              void* d_out, int out_size)
{
    const float*   query      = (const float*)d_in[0];
    const float*   query_pos  = (const float*)d_in[1];
    const float*   refpts     = (const float*)d_in[2];
    const float*   coords     = (const float*)d_in[3];
    const float*   dprobs     = (const float*)d_in[4];
    const int*     mask       = (const int*)d_in[5];
    const float*   layer_w1   = (const float*)d_in[6];
    const float*   layer_b1   = (const float*)d_in[7];
    const float*   layer_w2   = (const float*)d_in[8];
    const float*   layer_b2   = (const float*)d_in[9];
    const float*   prob_w     = (const float*)d_in[10];
    const float*   prob_b     = (const float*)d_in[11];
    const float*   pos_w      = (const float*)d_in[12];
    const float*   pos_b      = (const float*)d_in[13];
    const float*   g_w        = (const float*)d_in[14];
    const float*   g_b        = (const float*)d_in[15];
    const float*   be_w       = (const float*)d_in[16];
    const float*   be_b       = (const float*)d_in[17];
    const float*   pn_scale   = (const float*)d_in[18];
    const float*   pn_bias    = (const float*)d_in[19];
    float* out = (float*)d_out;

    float *q, *qp, *qs, *H, *lg, *S, *pb, *lnp, *t12, *ref, *w12, *b12;
    cudaGetSymbolAddress((void**)&q,   g_query);
    cudaGetSymbolAddress((void**)&qp,  g_qpos);
    cudaGetSymbolAddress((void**)&qs,  g_qsum);
    cudaGetSymbolAddress((void**)&H,   g_H);
    cudaGetSymbolAddress((void**)&lg,  g_logits);
    cudaGetSymbolAddress((void**)&S,   g_S);
    cudaGetSymbolAddress((void**)&pb,  g_probs);
    cudaGetSymbolAddress((void**)&lnp, g_lnpos);
    cudaGetSymbolAddress((void**)&t12, g_t12);
    cudaGetSymbolAddress((void**)&ref, g_ref);
    cudaGetSymbolAddress((void**)&w12, g_w12);
    cudaGetSymbolAddress((void**)&b12, g_b12);

    cudaFuncSetAttribute(tgemm<0>, cudaFuncAttributeMaxDynamicSharedMemorySize, GEMM_SMEM_BYTES);
    cudaFuncSetAttribute(tgemm<1>, cudaFuncAttributeMaxDynamicSharedMemorySize, GEMM_SMEM_BYTES);
    cudaFuncSetAttribute(tgemm<2>, cudaFuncAttributeMaxDynamicSharedMemorySize, GEMM_SMEM_BYTES);

    // init state
    cudaMemcpyAsync(q,   query,     (size_t)R_*C_*4, cudaMemcpyDeviceToDevice);
    cudaMemcpyAsync(qp,  query_pos, (size_t)R_*C_*4, cudaMemcpyDeviceToDevice);
    cudaMemcpyAsync(ref, refpts,    (size_t)R_*3*4,  cudaMemcpyDeviceToDevice);
    cudaMemcpyAsync(out + REFS_OFF, refpts, (size_t)R_*3*4, cudaMemcpyDeviceToDevice);

    pack_gb<<<(P_*512 + 255)/256, 256>>>(g_w, be_w, g_b, be_b, w12, b12);
    init_kernel<<<(R_*C_ + 255)/256, 256>>>(dprobs, lg, query, query_pos, qs);

    // pos_base = coords.reshape(R,384) @ pos_w + pos_b ; then LN -> g_lnpos
    tgemm<2><<<dim3(C_/128, R_/128), 128, GEMM_SMEM_BYTES>>>(R_, C_, P_*3, coords,
                                                             pos_w, pos_b, nullptr, t12);
    ln_rows<<<R_, 128>>>(t12, lnp);

    for (int i = 0; i < L_; i++) {
        // H = relu(qsum @ W1 + b1)
        tgemm<0><<<dim3(FF_/128, R_/128), 128, GEMM_SMEM_BYTES>>>(R_, FF_, C_,
            qs, layer_w1 + (size_t)i*C_*FF_, layer_b1 + (size_t)i*FF_, nullptr, H);
        // q = q + H @ W2 + b2
        tgemm<1><<<dim3(C_/128, R_/128), 128, GEMM_SMEM_BYTES>>>(R_, C_, FF_,
            H, layer_w2 + (size_t)i*FF_*C_, layer_b2 + (size_t)i*C_, q, q);
        // S = q @ prob_w + prob_b
        tgemm<2><<<dim3(P_/128, R_/128), 128, GEMM_SMEM_BYTES>>>(R_, P_, C_,
            q, prob_w + (size_t)i*C_*P_, prob_b + (size_t)i*P_, nullptr, S);
        // per-row fused ops
        row_kernel<<<R_, 128>>>(i, q, S, coords, mask, pn_scale, pn_bias,
                                lg, pb, ref, out);
        // [t1|t2] = probs @ [g_w|be_w] + [g_b|be_b]
        tgemm<2><<<dim3(512/128, R_/128), 128, GEMM_SMEM_BYTES>>>(R_, 512, P_,
            pb, w12, b12, nullptr, t12);
        // qpos masked update + qsum for next layer
        layer_tail<<<(R_*C_ + 255)/256, 256>>>(q, t12, lnp, mask, qp, qs);
    }
    (void)in_sizes; (void)n_in; (void)out_size;
}

// round 7
// speedup vs baseline: 1.7718x; 1.7370x over previous
#include <cuda_runtime.h>
#include <cuda_pipeline.h>
#include <cuda_fp16.h>
#include <mma.h>
#include <cstdint>
#include <cstddef>

using namespace nvcuda;

#define L_  6
#define B_  8
#define Q_  2048
#define C_  256
#define P_  128
#define FF_ 1024
#define R_  (B_*Q_)   // 16384 rows

static const size_t INTERM_OFF = 0;
static const size_t REFS_OFF   = (size_t)L_*R_*C_;                 // 25,165,824
static const size_t LOGITS_OFF = REFS_OFF + (size_t)(L_+1)*R_*3;   // 25,509,888

// ---------------- device state (no allocations allowed) ----------------
__device__ float  g_query [R_*C_];
__device__ float  g_qpos  [R_*C_];
__device__ float  g_H     [R_*FF_];
__device__ float  g_logits[R_*P_];
__device__ float  g_S     [R_*P_];
__device__ float  g_probs [R_*P_];
__device__ float  g_lnpos [R_*C_];
__device__ float  g_t12   [R_*512];
__device__ float  g_ref   [R_*3];
__device__ float  g_b12   [512];
// half activation copies (GEMM A operands)
__device__ __half g_qsum_h  [R_*C_];
__device__ __half g_H_h     [R_*FF_];
__device__ __half g_q_h     [R_*C_];
__device__ __half g_probs_h [R_*P_];
__device__ __half g_coords_h[R_*P_*3];
// half weights (GEMM B operands, natural [K,N] row-major)
__device__ __half g_w1h  [L_*C_*FF_];
__device__ __half g_w2h  [L_*FF_*C_];
__device__ __half g_probh[L_*C_*P_];
__device__ __half g_posh [(P_*3)*C_];
__device__ __half g_w12h [P_*512];

// ---------------- reductions ----------------
__device__ __forceinline__ float warp_sum(float v){
#pragma unroll
    for (int o = 16; o; o >>= 1) v += __shfl_xor_sync(0xffffffffu, v, o);
    return v;
}
__device__ __forceinline__ float warp_max(float v){
#pragma unroll
    for (int o = 16; o; o >>= 1) v = fmaxf(v, __shfl_xor_sync(0xffffffffu, v, o));
    return v;
}

// ---------------- pipelined FP16 GEMM, 64x64 warp tiles ----------------
// C = epi(A @ B + bias [+ Cres]); A [M,K] half, B [K,N] half, fp32 accum.
// BM=BN=128, BK=32, 3-stage cp.async. 128 threads = 4 warps (2x2), each 64x64
// = 4x4 wmma m16n16k16 frags. Epilogue via smem; optional half copy of C.
// EPI: 0=relu(.+b), 1=Cres+.+b, 2=.+b
#define GA_LD 40     // As row stride in halfs (32 + 8), 80B
#define GB_LD 136    // Bs row stride in halfs (128 + 8), 272B
#define ST_A (128*GA_LD)
#define ST_B (32*GB_LD)
#define CT_LD 132
#define TG_SMEM_BYTES (128*CT_LD*4)   // 67584 > 3*(ST_A+ST_B)*2 = 56832

template<int EPI, bool OUTH>
__global__ __launch_bounds__(128)
void hgemm(int M, int N, int K,
           const __half* __restrict__ A, const __half* __restrict__ Bm,
           const float* __restrict__ bias,
           const float* __restrict__ Cres, float* __restrict__ Cout,
           __half* __restrict__ CoutH)
{
    extern __shared__ __align__(16) char smx[];
    __half* Asm = (__half*)smx;              // [3][128][GA_LD]
    __half* Bsm = Asm + 3*ST_A;              // [3][32][GB_LD]

    const int tid = threadIdx.x;
    const int wid = tid >> 5;
    const int bm = blockIdx.y, bn = blockIdx.x;
    const int warp_m = wid >> 1;          // 0..1 -> 64 rows
    const int warp_n = wid & 1;           // 0..1 -> 64 cols

    // ---- stage loader (cp.async 16B = 8 halfs) ----
    auto load_stage = [&](int s, int k0) {
        __half* As = Asm + (size_t)s*ST_A;
        __half* Bs = Bsm + (size_t)s*ST_B;
#pragma unroll
        for (int i = 0; i < 4; i++) {
            int idx = tid + i * 128;           // 0..511
            // A: 128 rows x 32 halfs (4 chunks/row)
            int ar = idx >> 2, ac = (idx & 3) * 8;
            __pipeline_memcpy_async(As + ar*GA_LD + ac,
                A + (size_t)(bm*128 + ar)*K + k0 + ac, 16);
            // B: 32 rows x 128 halfs (16 chunks/row)
            int br = idx >> 4, bc = (idx & 15) * 8;
            __pipeline_memcpy_async(Bs + br*GB_LD + bc,
                Bm + (size_t)(k0 + br)*N + bn*128 + bc, 16);
        }
    };

    const int nIter = K / 32;
    load_stage(0, 0);
    __pipeline_commit();
    if (nIter > 1) load_stage(1, 32);
    __pipeline_commit();

    wmma::fragment<wmma::accumulator, 16, 16, 16, float> acc[4][4];
#pragma unroll
    for (int i = 0; i < 4; i++)
#pragma unroll
        for (int j = 0; j < 4; j++)
            wmma::fill_fragment(acc[i][j], 0.f);

    for (int it = 0; it < nIter; it++) {
        if (it + 2 < nIter) load_stage((it + 2) % 3, (it + 2) * 32);
        __pipeline_commit();
        __pipeline_wait_prior(2);
        __syncthreads();
        const __half* As = Asm + (size_t)(it % 3) * ST_A;
        const __half* Bs = Bsm + (size_t)(it % 3) * ST_B;
#pragma unroll
        for (int kk = 0; kk < 32; kk += 16) {
            wmma::fragment<wmma::matrix_a, 16, 16, 16, __half, wmma::row_major> af[4];
            wmma::fragment<wmma::matrix_b, 16, 16, 16, __half, wmma::row_major> bf[4];
#pragma unroll
            for (int i = 0; i < 4; i++)
                wmma::load_matrix_sync(af[i], As + (warp_m*64 + i*16)*GA_LD + kk, GA_LD);
#pragma unroll
            for (int j = 0; j < 4; j++)
                wmma::load_matrix_sync(bf[j], Bs + (size_t)kk*GB_LD + warp_n*64 + j*16, GB_LD);
#pragma unroll
            for (int i = 0; i < 4; i++)
#pragma unroll
                for (int j = 0; j < 4; j++)
                    wmma::mma_sync(acc[i][j], af[i], bf[j], acc[i][j]);
        }
        __syncthreads();
    }

    // ---- epilogue via smem (Ct overlaps pipeline buffers; all loads done) ----
    float* Ct = (float*)smx;   // [128][CT_LD]
#pragma unroll
    for (int i = 0; i < 4; i++)
#pragma unroll
        for (int j = 0; j < 4; j++)
            wmma::store_matrix_sync(
                Ct + (size_t)(warp_m*64 + i*16)*CT_LD + warp_n*64 + j*16,
                acc[i][j], CT_LD, wmma::mem_row_major);
    __syncthreads();

    {
        int grow = bm * 128 + tid;
        float* dst = Cout + (size_t)grow * N + bn * 128;
        __half* dsth = OUTH ? (CoutH + (size_t)grow * N + bn * 128) : nullptr;
        const float* bp = bias + bn * 128;
        const float* rp = (EPI == 1) ? (Cres + (size_t)grow * N + bn * 128) : nullptr;
#pragma unroll 4
        for (int c = 0; c < 128; c += 4) {
            float4 v = *(const float4*)&Ct[(size_t)tid * CT_LD + c];
            float4 b = *(const float4*)&bp[c];
            v.x += b.x; v.y += b.y; v.z += b.z; v.w += b.w;
            if (EPI == 0) {
                v.x = fmaxf(v.x, 0.f); v.y = fmaxf(v.y, 0.f);
                v.z = fmaxf(v.z, 0.f); v.w = fmaxf(v.w, 0.f);
            } else if (EPI == 1) {
                float4 cr = *(const float4*)&rp[c];
                v.x += cr.x; v.y += cr.y; v.z += cr.z; v.w += cr.w;
            }
            *(float4*)&dst[c] = v;
            if (OUTH) {
                __half2 h0 = __floats2half2_rn(v.x, v.y);
                __half2 h1 = __floats2half2_rn(v.z, v.w);
                uint2 u;
                u.x = *(uint32_t*)&h0;
                u.y = *(uint32_t*)&h1;
                *(uint2*)&dsth[c] = u;
            }
        }
    }
}

// ---------------- f32 -> f16 convert ----------------
__global__ void cvt_h(const float* __restrict__ src, __half* __restrict__ dst, int n)
{
    int i = blockIdx.x * blockDim.x + threadIdx.x;
    if (i < n) dst[i] = __float2half_rn(src[i]);
}

// ---------------- pack [g_b|be_b] fp32, [g_w|be_w] -> half ----------------
__global__ void pack_gb(const float* __restrict__ gw, const float* __restrict__ bew,
                        const float* __restrict__ gb, const float* __restrict__ beb,
                        __half* __restrict__ w12h, float* __restrict__ b12)
{
    int idx = blockIdx.x * blockDim.x + threadIdx.x;
    if (idx < P_ * 512) {
        int row = idx >> 9, col = idx & 511;
        float v = (col < 256) ? gw[row * 256 + col] : bew[row * 256 + col - 256];
        w12h[idx] = __float2half_rn(v);
    }
    if (idx < 512) b12[idx] = (idx < 256) ? gb[idx] : beb[idx - 256];
}

// ---------------- logits init + qsum init (fp16) ----------------
__global__ void init_kernel(const float* __restrict__ p, float* __restrict__ lg,
                            const float* __restrict__ q, const float* __restrict__ qp,
                            __half* __restrict__ qsum_h)
{
    int i = blockIdx.x * blockDim.x + threadIdx.x;
    if (i < R_*P_) lg[i] = logf(fmaxf(p[i], 1e-8f));
    if (i < R_*C_) qsum_h[i] = __float2half_rn(q[i] + qp[i]);
}

// ---------------- plain row LN (256 cols, 128 threads) ----------------
__global__ void ln_rows(const float* __restrict__ in, float* __restrict__ out)
{
    int row = blockIdx.x, t = threadIdx.x;
    int w = t >> 5, lane = t & 31;
    __shared__ float sr[8];
    float x0 = in[(size_t)row*C_ + t];
    float x1 = in[(size_t)row*C_ + 128 + t];
    float s1 = warp_sum(x0 + x1);
    float s2 = warp_sum(x0*x0 + x1*x1);
    if (lane == 0) { sr[w] = s1; sr[4+w] = s2; }
    __syncthreads();
    float m  = (sr[0]+sr[1]+sr[2]+sr[3]) * (1.f/256.f);
    float vv = (sr[4]+sr[5]+sr[6]+sr[7]) * (1.f/256.f) - m*m;
    float r  = rsqrtf(vv + 1e-5f);
    out[(size_t)row*C_ + t]       = (x0 - m) * r;
    out[(size_t)row*C_ + 128 + t] = (x1 - m) * r;
}

// ---------------- per-row fused: LN->interm, logits+softmax, ref einsum ----------------
__global__ void row_kernel(int layer,
                           const float* __restrict__ query,
                           const float* __restrict__ S,
                           const float* __restrict__ coords,
                           const int* __restrict__ mask,
                           const float* __restrict__ pn_scale,
                           const float* __restrict__ pn_bias,
                           float* __restrict__ logits_st,
                           float* __restrict__ probs,
                           __half* __restrict__ probs_h,
                           float* __restrict__ ref_st,
                           float* __restrict__ out)
{
    int row = blockIdx.x, t = threadIdx.x;
    int w = t >> 5, lane = t & 31;
    __shared__ float sr[12];

    float x0 = query[(size_t)row*C_ + t];
    float x1 = query[(size_t)row*C_ + 128 + t];
    float s1 = warp_sum(x0 + x1);
    float s2 = warp_sum(x0*x0 + x1*x1);
    if (lane == 0) { sr[w] = s1; sr[4+w] = s2; }
    __syncthreads();
    float m    = (sr[0]+sr[1]+sr[2]+sr[3]) * (1.f/256.f);
    float var  = (sr[4]+sr[5]+sr[6]+sr[7]) * (1.f/256.f) - m*m;
    float rstd = rsqrtf(var + 1e-5f);
    size_t ib = INTERM_OFF + (size_t)layer*R_*C_ + (size_t)row*C_;
    out[ib + t]       = (x0 - m)*rstd*pn_scale[t]       + pn_bias[t];
    out[ib + 128 + t] = (x1 - m)*rstd*pn_scale[128 + t] + pn_bias[128 + t];

    float mf = mask[row] ? 1.f : 0.f;
    size_t li = (size_t)row*P_ + t;
    float lg = logits_st[li] + S[li] * mf;
    logits_st[li] = lg;
    out[LOGITS_OFF + (size_t)layer*R_*P_ + li] = lg;

    float mx = warp_max(lg);
    __syncthreads();
    if (lane == 0) sr[w] = mx;
    __syncthreads();
    mx = fmaxf(fmaxf(sr[0], sr[1]), fmaxf(sr[2], sr[3]));
    float e = __expf(lg - mx);
    float se = warp_sum(e);
    __syncthreads();
    if (lane == 0) sr[w] = se;
    __syncthreads();
    se = sr[0]+sr[1]+sr[2]+sr[3];
    float p = e / se;
    probs[li] = p;
    probs_h[li] = __float2half_rn(p);

    const float* cr = coords + (size_t)row*P_*3 + (size_t)t*3;
    float r0 = warp_sum(p * cr[0]);
    float r1 = warp_sum(p * cr[1]);
    float r2 = warp_sum(p * cr[2]);
    __syncthreads();
    if (lane == 0) { sr[w] = r0; sr[4+w] = r1; sr[8+w] = r2; }
    __syncthreads();
    if (t == 0) {
        float d0 = sr[0]+sr[1]+sr[2]+sr[3];
        float d1 = sr[4]+sr[5]+sr[6]+sr[7];
        float d2 = sr[8]+sr[9]+sr[10]+sr[11];
        float o0, o1, o2;
        if (mf > 0.f) { o0 = d0; o1 = d1; o2 = d2; }
        else { o0 = ref_st[row*3]; o1 = ref_st[row*3+1]; o2 = ref_st[row*3+2]; }
        ref_st[row*3] = o0; ref_st[row*3+1] = o1; ref_st[row*3+2] = o2;
        size_t rb = REFS_OFF + (size_t)(layer+1)*R_*3 + (size_t)row*3;
        out[rb] = o0; out[rb+1] = o1; out[rb+2] = o2;
    }
}

// ---------------- layer tail: masked qpos update + qsum_h = h(q + qpos) ----------------
__global__ void layer_tail(const float* __restrict__ q,
                           const float* __restrict__ t12,
                           const float* __restrict__ lnp, const int* __restrict__ mask,
                           float* __restrict__ qpos, __half* __restrict__ qsum_h)
{
    int idx = blockIdx.x * blockDim.x + threadIdx.x;
    if (idx >= R_*C_) return;
    int row = idx >> 8, c = idx & 255;
    float qp = qpos[idx];
    if (mask[row]) {
        float t1 = t12[(size_t)row*512 + c];
        float t2 = t12[(size_t)row*512 + 256 + c];
        qp = lnp[idx] * t1 + t2;
        qpos[idx] = qp;
    }
    qsum_h[idx] = __float2half_rn(q[idx] + qp);
}

// ---------------- host ----------------
extern "C" void kernel_launch(void* const* d_in, const int* in_sizes, int n_in,
                              void* d_out, int out_size)
{
    const float*   query      = (const float*)d_in[0];
    const float*   query_pos  = (const float*)d_in[1];
    const float*   refpts     = (const float*)d_in[2];
    const float*   coords     = (const float*)d_in[3];
    const float*   dprobs     = (const float*)d_in[4];
    const int*     mask       = (const int*)d_in[5];
    const float*   layer_w1   = (const float*)d_in[6];
    const float*   layer_b1   = (const float*)d_in[7];
    const float*   layer_w2   = (const float*)d_in[8];
    const float*   layer_b2   = (const float*)d_in[9];
    const float*   prob_w     = (const float*)d_in[10];
    const float*   prob_b     = (const float*)d_in[11];
    const float*   pos_w      = (const float*)d_in[12];
    const float*   pos_b      = (const float*)d_in[13];
    const float*   g_wp       = (const float*)d_in[14];
    const float*   g_bp       = (const float*)d_in[15];
    const float*   be_w       = (const float*)d_in[16];
    const float*   be_b       = (const float*)d_in[17];
    const float*   pn_scale   = (const float*)d_in[18];
    const float*   pn_bias    = (const float*)d_in[19];
    float* out = (float*)d_out;

    float *q, *qp, *H, *lg, *S, *pb, *lnp, *t12, *ref, *b12;
    __half *qsh, *Hh, *qh, *pbh, *coh, *w1h, *w2h, *prh, *psh, *w12h;
    cudaGetSymbolAddress((void**)&q,    g_query);
    cudaGetSymbolAddress((void**)&qp,   g_qpos);
    cudaGetSymbolAddress((void**)&H,    g_H);
    cudaGetSymbolAddress((void**)&lg,   g_logits);
    cudaGetSymbolAddress((void**)&S,    g_S);
    cudaGetSymbolAddress((void**)&pb,   g_probs);
    cudaGetSymbolAddress((void**)&lnp,  g_lnpos);
    cudaGetSymbolAddress((void**)&t12,  g_t12);
    cudaGetSymbolAddress((void**)&ref,  g_ref);
    cudaGetSymbolAddress((void**)&b12,  g_b12);
    cudaGetSymbolAddress((void**)&qsh,  g_qsum_h);
    cudaGetSymbolAddress((void**)&Hh,   g_H_h);
    cudaGetSymbolAddress((void**)&qh,   g_q_h);
    cudaGetSymbolAddress((void**)&pbh,  g_probs_h);
    cudaGetSymbolAddress((void**)&coh,  g_coords_h);
    cudaGetSymbolAddress((void**)&w1h,  g_w1h);
    cudaGetSymbolAddress((void**)&w2h,  g_w2h);
    cudaGetSymbolAddress((void**)&prh,  g_probh);
    cudaGetSymbolAddress((void**)&psh,  g_posh);
    cudaGetSymbolAddress((void**)&w12h, g_w12h);

    cudaFuncSetAttribute(hgemm<0,true>,  cudaFuncAttributeMaxDynamicSharedMemorySize, TG_SMEM_BYTES);
    cudaFuncSetAttribute(hgemm<1,true>,  cudaFuncAttributeMaxDynamicSharedMemorySize, TG_SMEM_BYTES);
    cudaFuncSetAttribute(hgemm<2,false>, cudaFuncAttributeMaxDynamicSharedMemorySize, TG_SMEM_BYTES);

    // init fp32 state
    cudaMemcpyAsync(q,   query,  (size_t)R_*C_*4, cudaMemcpyDeviceToDevice);
    cudaMemcpyAsync(ref, refpts, (size_t)R_*3*4,  cudaMemcpyDeviceToDevice);
    cudaMemcpyAsync(qp,  query_pos, (size_t)R_*C_*4, cudaMemcpyDeviceToDevice);
    cudaMemcpyAsync(out + REFS_OFF, refpts, (size_t)R_*3*4, cudaMemcpyDeviceToDevice);

    // weight/input conversions (once)
    cvt_h<<<(L_*C_*FF_ + 255)/256, 256>>>(layer_w1, w1h, L_*C_*FF_);
    cvt_h<<<(L_*FF_*C_ + 255)/256, 256>>>(layer_w2, w2h, L_*FF_*C_);
    cvt_h<<<(L_*C_*P_ + 255)/256, 256>>>(prob_w, prh, L_*C_*P_);
    cvt_h<<<((P_*3)*C_ + 255)/256, 256>>>(pos_w, psh, (P_*3)*C_);
    cvt_h<<<(R_*P_*3 + 255)/256, 256>>>(coords, coh, R_*P_*3);
    pack_gb<<<(P_*512 + 255)/256, 256>>>(g_wp, be_w, g_bp, be_b, w12h, b12);
    init_kernel<<<(R_*C_ + 255)/256, 256>>>(dprobs, lg, query, query_pos, qsh);

    // pos_base = coords @ pos_w + pos_b ; then LN -> g_lnpos
    hgemm<2,false><<<dim3(C_/128, R_/128), 128, TG_SMEM_BYTES>>>(R_, C_, P_*3,
        coh, psh, pos_b, nullptr, t12, nullptr);
    ln_rows<<<R_, 128>>>(t12, lnp);

    for (int i = 0; i < L_; i++) {
        // H = relu(qsum @ W1 + b1)  (+ half copy)
        hgemm<0,true><<<dim3(FF_/128, R_/128), 128, TG_SMEM_BYTES>>>(R_, FF_, C_,
            qsh, w1h + (size_t)i*C_*FF_, layer_b1 + (size_t)i*FF_, nullptr, H, Hh);
        // q = q + H @ W2 + b2  (+ half copy)
        hgemm<1,true><<<dim3(C_/128, R_/128), 128, TG_SMEM_BYTES>>>(R_, C_, FF_,
            Hh, w2h + (size_t)i*FF_*C_, layer_b2 + (size_t)i*C_, q, q, qh);
        // S = q @ prob_w + prob_b
        hgemm<2,false><<<dim3(P_/128, R_/128), 128, TG_SMEM_BYTES>>>(R_, P_, C_,
            qh, prh + (size_t)i*C_*P_, prob_b + (size_t)i*P_, nullptr, S, nullptr);
        // per-row fused ops
        row_kernel<<<R_, 128>>>(i, q, S, coords, mask, pn_scale, pn_bias,
                                lg, pb, pbh, ref, out);
        // [t1|t2] = probs @ [g_w|be_w] + [g_b|be_b]
        hgemm<2,false><<<dim3(512/128, R_/128), 128, TG_SMEM_BYTES>>>(R_, 512, P_,
            pbh, w12h, b12, nullptr, t12, nullptr);
        // qpos masked update + qsum_h for next layer
        layer_tail<<<(R_*C_ + 255)/256, 256>>>(q, t12, lnp, mask, qp, qsh);
    }
    (void)in_sizes; (void)n_in; (void)out_size;
}